// round 17
// baseline (speedup 1.0000x reference)
#include <cuda_runtime.h>
#include <cuda_bf16.h>
#include <math.h>
#include <stdint.h>

#define BB 16
#define CN 64

// ---- scratch (hi/lo interleaved as uint2) ----
__device__ uint2  g_Y1p[BB*CN*256*32];
__device__ float2 g_Xf [BB*CN*64*32];
__device__ float2 g_T  [BB*CN*64*32];            // [b][kxi][ky][c]
__device__ uint2  g_OFp[BB*CN*64*32];
__device__ float  g_Z  [BB*CN*256*64];
// stationary packed planes
__device__ uint2 g_B1p[64*128];
__device__ uint2 g_A2p[128*256];
__device__ uint2 g_A5p[512*64];
__device__ uint2 g_C6p[256*32];
__device__ uint2 g_WXp[64*128*64];
__device__ uint2 g_WYp[32*128*64];

__device__ __forceinline__ uint2 packsplit(float a, float b) {
    __nv_bfloat162 hv = __floats2bfloat162_rn(a, b);
    __nv_bfloat162 lv = __floats2bfloat162_rn(a - __bfloat162float(hv.x),
                                              b - __bfloat162float(hv.y));
    return make_uint2(*(unsigned*)&hv, *(unsigned*)&lv);
}
__device__ __forceinline__ void mmab(float* c, const unsigned* a, const unsigned* b) {
    asm volatile(
        "mma.sync.aligned.m16n8k16.row.col.f32.bf16.bf16.f32 "
        "{%0,%1,%2,%3},{%4,%5,%6,%7},{%8,%9},{%0,%1,%2,%3};"
        : "+f"(c[0]), "+f"(c[1]), "+f"(c[2]), "+f"(c[3])
        : "r"(a[0]), "r"(a[1]), "r"(a[2]), "r"(a[3]), "r"(b[0]), "r"(b[1]));
}
__device__ __forceinline__ void mma3v(float* c, const uint2* a, const uint2* b) {
    unsigned ah[4] = {a[0].x, a[1].x, a[2].x, a[3].x};
    unsigned al[4] = {a[0].y, a[1].y, a[2].y, a[3].y};
    unsigned bh[2] = {b[0].x, b[1].x};
    unsigned bl[2] = {b[0].y, b[1].y};
    mmab(c, ah, bh); mmab(c, al, bh); mmab(c, ah, bl);
}

// ---- fills (unchanged R15) ----
__global__ void __launch_bounds__(256) fill_all() {
    int idx = blockIdx.x * 256 + threadIdx.x;   // 32768
    {   int m = idx >> 8, k2 = idx & 255;
        int kxi = m >> 1, t = m & 1, kx = (kxi < 32) ? kxi : 192 + kxi;
        float s, c; sincospif((float)((kx * k2) & 255) / 128.0f, &s, &c);
        g_A2p[idx] = packsplit((t ? -s : c) * (1.0f/16.0f), (t ? c : s) * (1.0f/16.0f));
    }
    {   int m = idx >> 6, k2 = idx & 63;
        int h = m >> 1, t = m & 1, kx = (k2 < 32) ? k2 : 192 + k2;
        float s, c; sincospif((float)((kx * h) & 255) / 128.0f, &s, &c);
        g_A5p[idx] = packsplit((t ? s : c), (t ? c : -s));
    }
    if (idx < 8192) {
        int n = idx >> 7, k2 = idx & 127;
        int ky = n >> 1, t = n & 1;
        float s0, c0, s1, c1;
        sincospif((float)(((2*k2) * ky) & 255) / 128.0f, &s0, &c0);
        sincospif((float)(((2*k2+1) * ky) & 255) / 128.0f, &s1, &c1);
        g_B1p[idx] = packsplit((t ? -s0 : c0) * (1.0f/16.0f), (t ? -s1 : c1) * (1.0f/16.0f));
    }
    if (idx < 8192) {
        int w = idx >> 5, ky = idx & 31;
        float s, c; sincospif((float)((ky * w) & 255) / 128.0f, &s, &c);
        float base = ((ky == 0) ? 1.0f : 2.0f) * (1.0f/256.0f);
        g_C6p[idx] = packsplit(base * c, (ky == 0) ? 0.0f : -base * s);
    }
}
__global__ void __launch_bounds__(256) fill_w(const float* __restrict__ wx1,
                                              const float* __restrict__ wx2,
                                              const float* __restrict__ wy) {
    int idx = blockIdx.x * 256 + threadIdx.x;   // 786432
    if (idx < 524288) {
        int k2 = idx & 63, n = (idx >> 6) & 127, m = idx >> 13;
        const float2* src = (const float2*)((m < 32) ? wx1 : wx2);
        float2 w = src[(k2 * 64 + (n >> 1)) * 32 + (m & 31)];
        g_WXp[idx] = packsplit((n & 1) ? w.y : w.x, (n & 1) ? w.x : -w.y);
    } else {
        int r = idx - 524288;
        int k2 = r & 63, n = (r >> 6) & 127;
        float2 w = ((const float2*)wy)[(k2 * 64 + (n >> 1)) * 32 + (r >> 13)];
        g_WYp[r] = packsplit((n & 1) ? w.y : w.x, (n & 1) ? w.x : -w.y);
    }
}

// ---- S1 (512t, M=256/CTA): Y1 = x @ B1 ----
__global__ void __launch_bounds__(512) s1_wdft(const float* __restrict__ x) {
    __shared__ uint2 sX[256][17], sB[64][17];   // 43.5KB
    const int tid = threadIdx.x, warp = tid >> 5, lane = tid & 31;
    const int g = lane >> 2, tg = lane & 3;
    const size_t r0 = (size_t)blockIdx.x * 256;
    float c[8][4];
#pragma unroll
    for (int i = 0; i < 8; i++) { c[i][0]=c[i][1]=c[i][2]=c[i][3]=0.f; }
    for (int kc = 0; kc < 8; kc++) {
        __syncthreads();
        for (int i = tid; i < 4096; i += 512) {
            int row = i >> 4, col = i & 15;
            float2 v = *(const float2*)&x[(r0 + row) * 256 + kc * 32 + 2 * col];
            sX[row][col] = packsplit(v.x, v.y);
        }
        for (int i = tid; i < 1024; i += 512) {
            int n = i >> 4, col = i & 15;
            sB[n][col] = g_B1p[n * 128 + kc * 16 + col];
        }
        __syncthreads();
#pragma unroll
        for (int ks = 0; ks < 2; ks++) {
            int r = warp * 16 + g, k0 = ks * 8 + tg;
            uint2 a[4] = {sX[r][k0], sX[r+8][k0], sX[r][k0+4], sX[r+8][k0+4]};
#pragma unroll
            for (int nt = 0; nt < 8; nt++) {
                int n = nt * 8 + g;
                uint2 b[2] = {sB[n][k0], sB[n][k0+4]};
                mma3v(c[nt], a, b);
            }
        }
    }
#pragma unroll
    for (int nt = 0; nt < 8; nt++) {
        size_t m = r0 + warp * 16 + g;
        int ky = nt * 4 + tg;
        g_Y1p[m * 32 + ky]       = packsplit(c[nt][0], c[nt][1]);
        g_Y1p[(m + 8) * 32 + ky] = packsplit(c[nt][2], c[nt][3]);
    }
}

// ---- S2 (512t, batch 4): two warp-groups x 2 slabs ----
__global__ void __launch_bounds__(512) s2_hdft() {
    __shared__ uint2 sA[128][17];         // 17.4KB
    __shared__ uint2 sY[4][16][33];       // 16.9KB
    const int tid = threadIdx.x, warp = tid >> 5, lane = tid & 31;
    const int g = lane >> 2, tg = lane & 3;
    const int w8 = warp & 7, wg = warp >> 3;
    const int bi0 = blockIdx.x * 4;
    float c[2][4][4];
#pragma unroll
    for (int s = 0; s < 2; s++)
#pragma unroll
        for (int i = 0; i < 4; i++) { c[s][i][0]=c[s][i][1]=c[s][i][2]=c[s][i][3]=0.f; }

    for (int kc = 0; kc < 16; kc++) {
        __syncthreads();
        for (int i = tid; i < 2048; i += 512) {
            int row = i >> 4, col = i & 15;
            sA[row][col] = g_A2p[row * 256 + kc * 16 + col];
        }
        for (int i = tid; i < 2048; i += 512) {
            int sl = i >> 9, rem = i & 511;
            int hl = rem >> 5, ky = rem & 31;
            sY[sl][hl][ky] = g_Y1p[((size_t)(bi0 + sl) * 256 + kc * 16 + hl) * 32 + ky];
        }
        __syncthreads();
#pragma unroll
        for (int ks = 0; ks < 2; ks++) {
            int r = w8 * 16 + g, k0 = ks * 8 + tg;
            uint2 a[4] = {sA[r][k0], sA[r+8][k0], sA[r][k0+4], sA[r+8][k0+4]};
#pragma unroll
            for (int s = 0; s < 2; s++) {
                int sl = wg * 2 + s;
#pragma unroll
                for (int nt = 0; nt < 4; nt++) {
                    int n = nt * 8 + g;
                    uint2 b[2] = {sY[sl][k0][n], sY[sl][k0+4][n]};
                    mma3v(c[s][nt], a, b);
                }
            }
        }
    }
#pragma unroll
    for (int s = 0; s < 2; s++) {
        float* xf = (float*)g_Xf + (size_t)(bi0 + wg * 2 + s) * 4096;
#pragma unroll
        for (int nt = 0; nt < 4; nt++) {
            int m0 = w8 * 16 + g, m1 = m0 + 8;
            int n0 = nt * 8 + 2 * tg, n1 = n0 + 1;
            xf[(m0 >> 1) * 64 + 2 * n0 + (m0 & 1)] = c[s][nt][0];
            xf[(m0 >> 1) * 64 + 2 * n1 + (m0 & 1)] = c[s][nt][1];
            xf[(m1 >> 1) * 64 + 2 * n0 + (m1 & 1)] = c[s][nt][2];
            xf[(m1 >> 1) * 64 + 2 * n1 + (m1 & 1)] = c[s][nt][3];
        }
    }
}

// ---- K3a (unchanged R15) ----
#define K3A_SMEM ((32*65 + 128*65) * 8)
__global__ void __launch_bounds__(256) k3a_mma() {
    extern __shared__ uint2 sm[];
    uint2* sA = sm;
    uint2* sB = sA + 32*65;
    const int tid = threadIdx.x, warp = tid >> 5, lane = tid & 31;
    const int g = lane >> 2, tg = lane & 3;
    const int kxi = blockIdx.x, bg = blockIdx.y;
    const int mt = warp >> 2, ng = warp & 3;

    for (int i = tid; i < 8192; i += 256) {
        int n = i >> 6, k2 = i & 63;
        sB[n*65 + k2] = g_WXp[((size_t)kxi*128 + n)*64 + k2];
    }
    const float* xf = (const float*)g_Xf;
    for (int bb = 0; bb < 4; bb++) {
        int b = bg * 4 + bb;
        __syncthreads();
        for (int i = tid; i < 2048; i += 256) {
            int ky = i & 31, ic = i >> 5;
            float2 v = *(const float2*)&xf[((size_t)(b*64 + ic))*4096 + kxi*64 + 2*ky];
            sA[ky*65 + ic] = packsplit(v.x, v.y);
        }
        __syncthreads();
        float c[4][4];
#pragma unroll
        for (int i = 0; i < 4; i++) { c[i][0]=c[i][1]=c[i][2]=c[i][3]=0.f; }
#pragma unroll
        for (int ks = 0; ks < 8; ks++) {
            int r = mt*16 + g, k0 = ks*8 + tg;
            uint2 a[4] = {sA[r*65+k0], sA[(r+8)*65+k0], sA[r*65+k0+4], sA[(r+8)*65+k0+4]};
#pragma unroll
            for (int j = 0; j < 4; j++) {
                int n = (ng*4 + j)*8 + g;
                uint2 bfr[2] = {sB[n*65+k0], sB[n*65+k0+4]};
                mma3v(c[j], a, bfr);
            }
        }
#pragma unroll
        for (int j = 0; j < 4; j++) {
            int ch = (ng*4 + j)*4 + tg;
            int ky0 = mt*16 + g;
            g_T[(((size_t)b*64 + kxi)*32 + ky0)*64 + ch]     = make_float2(c[j][0], c[j][1]);
            g_T[(((size_t)b*64 + kxi)*32 + ky0 + 8)*64 + ch] = make_float2(c[j][2], c[j][3]);
        }
    }
}

// ---- K3b (unchanged R15) ----
#define K3B_SMEM ((64*65 + 128*65) * 8)
__global__ void __launch_bounds__(256) k3b_mma() {
    extern __shared__ uint2 sm[];
    uint2* sA = sm;
    uint2* sB = sA + 64*65;
    const int tid = threadIdx.x, warp = tid >> 5, lane = tid & 31;
    const int g = lane >> 2, tg = lane & 3;
    const int ky = blockIdx.x, bg = blockIdx.y;
    const int mt = warp >> 1, ng = warp & 1;

    for (int i = tid; i < 8192; i += 256) {
        int n = i >> 6, k2 = i & 63;
        sB[n*65 + k2] = g_WYp[((size_t)ky*128 + n)*64 + k2];
    }
    for (int bb = 0; bb < 2; bb++) {
        int b = bg * 2 + bb;
        __syncthreads();
        for (int i = tid; i < 4096; i += 256) {
            int c2 = i & 63, kxi = i >> 6;
            float2 v = g_T[(((size_t)b*64 + kxi)*32 + ky)*64 + c2];
            sA[kxi*65 + c2] = packsplit(v.x, v.y);
        }
        __syncthreads();
        float c[8][4];
#pragma unroll
        for (int i = 0; i < 8; i++) { c[i][0]=c[i][1]=c[i][2]=c[i][3]=0.f; }
#pragma unroll
        for (int ks = 0; ks < 8; ks++) {
            int r = mt*16 + g, k0 = ks*8 + tg;
            uint2 a[4] = {sA[r*65+k0], sA[(r+8)*65+k0], sA[r*65+k0+4], sA[(r+8)*65+k0+4]};
#pragma unroll
            for (int j = 0; j < 8; j++) {
                int n = (ng*8 + j)*8 + g;
                uint2 bfr[2] = {sB[n*65+k0], sB[n*65+k0+4]};
                mma3v(c[j], a, bfr);
            }
        }
#pragma unroll
        for (int j = 0; j < 8; j++) {
            int o = (ng*8 + j)*4 + tg;
            int kxi0 = mt*16 + g;
            g_OFp[(((size_t)b*64 + o)*64 + kxi0)*32 + ky]     = packsplit(c[j][0], c[j][1]);
            g_OFp[(((size_t)b*64 + o)*64 + kxi0 + 8)*32 + ky] = packsplit(c[j][2], c[j][3]);
        }
    }
}

// ---- S5 (512t, batch 4 bo): Z = A5 @ OutF ----
#define S5_SMEM ((256*9 + 4*64*33) * 8)
__global__ void __launch_bounds__(512) s5_invh() {
    extern __shared__ uint2 sm5[];
    uint2* sA = sm5;                 // [256][9]
    uint2* sF = sA + 256*9;          // [4][64][33]
    const int tid = threadIdx.x, warp = tid >> 5, lane = tid & 31;
    const int g = lane >> 2, tg = lane & 3;
    const int w8 = warp & 7, wg = warp >> 3;
    const int mh = blockIdx.x, bo0 = blockIdx.y * 4;

    for (int i = tid; i < 8192; i += 512) {
        int bl = i >> 11, rem = i & 2047;
        sF[bl*2112 + (rem >> 5)*33 + (rem & 31)] = g_OFp[(size_t)(bo0 + bl) * 2048 + rem];
    }
    float c[2][2][4][4];
#pragma unroll
    for (int s = 0; s < 2; s++)
#pragma unroll
        for (int a = 0; a < 2; a++)
#pragma unroll
            for (int i = 0; i < 4; i++) { c[s][a][i][0]=c[s][a][i][1]=c[s][a][i][2]=c[s][a][i][3]=0.f; }

    for (int kc = 0; kc < 8; kc++) {
        __syncthreads();
        for (int i = tid; i < 2048; i += 512) {
            int row = i >> 3, col = i & 7;
            sA[row*9 + col] = g_A5p[(mh * 256 + row) * 64 + kc * 8 + col];
        }
        __syncthreads();
        uint2 bfr[2][4][2];
#pragma unroll
        for (int s = 0; s < 2; s++) {
            const uint2* f = sF + (wg * 2 + s) * 2112;
#pragma unroll
            for (int nt = 0; nt < 4; nt++) {
                int n = nt * 8 + g;
                bfr[s][nt][0] = f[(kc*8+tg)*33 + n];
                bfr[s][nt][1] = f[(kc*8+tg+4)*33 + n];
            }
        }
#pragma unroll
        for (int mt = 0; mt < 2; mt++) {
            int r = w8 * 32 + mt * 16 + g;
            uint2 a[4] = {sA[r*9+tg], sA[(r+8)*9+tg], sA[r*9+tg+4], sA[(r+8)*9+tg+4]};
#pragma unroll
            for (int s = 0; s < 2; s++)
#pragma unroll
                for (int nt = 0; nt < 4; nt++)
                    mma3v(c[s][mt][nt], a, bfr[s][nt]);
        }
    }
#pragma unroll
    for (int s = 0; s < 2; s++) {
        float* z = g_Z + (size_t)(bo0 + wg * 2 + s) * 16384;
#pragma unroll
        for (int mt = 0; mt < 2; mt++)
#pragma unroll
            for (int nt = 0; nt < 4; nt++) {
                int m0 = mh * 256 + w8 * 32 + mt * 16 + g, m1 = m0 + 8;
                int n0 = nt * 8 + 2 * tg, n1 = n0 + 1;
                z[(m0 >> 1) * 64 + 2 * n0 + (m0 & 1)] = c[s][mt][nt][0];
                z[(m0 >> 1) * 64 + 2 * n1 + (m0 & 1)] = c[s][mt][nt][1];
                z[(m1 >> 1) * 64 + 2 * n0 + (m1 & 1)] = c[s][mt][nt][2];
                z[(m1 >> 1) * 64 + 2 * n1 + (m1 & 1)] = c[s][mt][nt][3];
            }
    }
}

// ---- S6 (unchanged R15) ----
__global__ void __launch_bounds__(256) s6_invw(float* __restrict__ out) {
    __shared__ uint2 sZ[128][17], sC[128][17];
    const int tid = threadIdx.x, warp = tid >> 5, lane = tid & 31;
    const int g = lane >> 2, tg = lane & 3;
    const int mt2 = blockIdx.x, nt2 = blockIdx.y, bo = blockIdx.z;
    float c[16][4];
#pragma unroll
    for (int i = 0; i < 16; i++) { c[i][0]=c[i][1]=c[i][2]=c[i][3]=0.f; }
    const float* z = g_Z + (size_t)bo * 16384;
    for (int kc = 0; kc < 2; kc++) {
        __syncthreads();
        for (int i = tid; i < 2048; i += 256) {
            int row = i >> 4, col = i & 15;
            float2 zv = *(const float2*)&z[(mt2 * 128 + row) * 64 + kc * 32 + 2 * col];
            sZ[row][col] = packsplit(zv.x, zv.y);
        }
        for (int i = tid; i < 2048; i += 256) {
            int nl = i >> 4, col = i & 15;
            sC[nl][col] = g_C6p[(nt2 * 128 + nl) * 32 + kc * 16 + col];
        }
        __syncthreads();
#pragma unroll
        for (int ks = 0; ks < 2; ks++) {
            int r = warp * 16 + g, k0 = ks * 8 + tg;
            uint2 a[4] = {sZ[r][k0], sZ[r+8][k0], sZ[r][k0+4], sZ[r+8][k0+4]};
#pragma unroll
            for (int nt = 0; nt < 16; nt++) {
                int n = nt * 8 + g;
                uint2 bfr[2] = {sC[n][k0], sC[n][k0+4]};
                mma3v(c[nt], a, bfr);
            }
        }
    }
    float* orow = out + (size_t)bo * 65536;
#pragma unroll
    for (int nt = 0; nt < 16; nt++) {
        int h = mt2 * 128 + warp * 16 + g;
        int w = nt2 * 128 + nt * 8 + 2 * tg;
        *(float2*)&orow[(h)     * 256 + w] = make_float2(c[nt][0], c[nt][1]);
        *(float2*)&orow[(h + 8) * 256 + w] = make_float2(c[nt][2], c[nt][3]);
    }
}

extern "C" void kernel_launch(void* const* d_in, const int* in_sizes, int n_in,
                              void* d_out, int out_size) {
    const float* x   = (const float*)d_in[0];
    const float* wx1 = (const float*)d_in[1];
    const float* wx2 = (const float*)d_in[2];
    const float* wy  = (const float*)d_in[3];
    float* out = (float*)d_out;

    cudaFuncSetAttribute(k3a_mma, cudaFuncAttributeMaxDynamicSharedMemorySize, K3A_SMEM);
    cudaFuncSetAttribute(k3b_mma, cudaFuncAttributeMaxDynamicSharedMemorySize, K3B_SMEM);
    cudaFuncSetAttribute(s5_invh, cudaFuncAttributeMaxDynamicSharedMemorySize, S5_SMEM);

    fill_all<<<128, 256>>>();
    fill_w<<<3072, 256>>>(wx1, wx2, wy);
    s1_wdft<<<1024, 512>>>(x);
    s2_hdft<<<256, 512>>>();
    k3a_mma<<<dim3(64, 4), 256, K3A_SMEM>>>();
    k3b_mma<<<dim3(32, 8), 256, K3B_SMEM>>>();
    s5_invh<<<dim3(2, 256), 512, S5_SMEM>>>();
    s6_invw<<<dim3(2, 2, 1024), 256>>>(out);
}